// round 2
// baseline (speedup 1.0000x reference)
#include <cuda_runtime.h>
#include <cuda_bf16.h>

typedef unsigned long long ull;

#define BETA_F   0.99f
#define EPS_V_F  1e-3f
#define ABS2_MASK 0x7FFFFFFF7FFFFFFFull

// per-block partial sums + completion counter (deterministic single-kernel reduction)
__device__ float g_partials[16384];
__device__ int   g_count = 0;

// ---------- packed f32x2 helpers ----------
__device__ __forceinline__ ull pack2(float lo, float hi) {
    ull r;
    asm("mov.b64 %0, {%1, %2};" : "=l"(r) : "f"(lo), "f"(hi));
    return r;
}
__device__ __forceinline__ void unpack2(ull v, float& lo, float& hi) {
    asm("mov.b64 {%0, %1}, %2;" : "=f"(lo), "=f"(hi) : "l"(v));
}
__device__ __forceinline__ ull fma2(ull a, ull b, ull c) {
    ull d;
    asm("fma.rn.f32x2 %0, %1, %2, %3;" : "=l"(d) : "l"(a), "l"(b), "l"(c));
    return d;
}

// ---------- per-row epilogue ----------
__device__ __forceinline__ float row_epilogue(
    float x0, float x1,
    float mu0, float mu1, float l0, float l1,
    float y0, float y1, float e0, float e1,
    const float* __restrict__ wv,
    float& f0, float& f1)
{
    float u0 = fmaf(x1, wv[2], x0 * wv[0]);
    float u1 = fmaf(x1, wv[3], x0 * wv[1]);
    float vx = fmaf(u1, u1, fmaf(u0, u0, EPS_V_F));
    float m0 = fmaf(mu1, wv[2], mu0 * wv[0]);
    float m1 = fmaf(mu1, wv[3], mu0 * wv[1]);
    float vmu = fmaf(m1, m1, fmaf(m0, m0, EPS_V_F));
    float bvx = BETA_F * vx;
    float s   = __fdividef(fminf(bvx, vmu), vmu);
    float ms0 = mu0 * s;
    float ms1 = mu1 * s;
    float sd0 = __expf(0.5f * l0);
    float sd1 = __expf(0.5f * l1);
    float iv0 = __expf(-l0);
    float iv1 = __expf(-l1);
    f0 = fmaf(sd0, e0, ms0);
    f1 = fmaf(sd1, e1, ms1);
    float d0 = y0 - ms0;
    float d1 = y1 - ms1;
    return fmaf(d0 * d0, iv0, fmaf(d1 * d1, iv1, l0 + l1));
}

// ---------- fused kernel: MLP (abs-reformulated) + epilogue + full reduction ----------
__global__ __launch_bounds__(256) void mdn_kernel(
    const float* __restrict__ x, const float* __restrict__ y, const float* __restrict__ eps,
    const float* __restrict__ W1, const float* __restrict__ b1,
    const float* __restrict__ W2, const float* __restrict__ b2,
    const float* __restrict__ Wv,
    float* __restrict__ out, long long B)
{
    // relu(u) = (u + |u|)/2  =>  out = P^T xvec + q + sum_j (0.5*w2_j)|u_j|
    __shared__ ulonglong2 sW1[64];   // .x = dup(W1[0][j]), .y = dup(W1[1][j])
    __shared__ ull        sB1[64];   // dup(b1[j])
    __shared__ ulonglong2 sW2a[64];  // {dup(.5*W2[j][0]), dup(.5*W2[j][1])}
    __shared__ ulonglong2 sW2b[64];  // {dup(.5*W2[j][2]), dup(.5*W2[j][3])}
    __shared__ float      sP[8];     // P[i][k] = .5*sum_j W1[i][j]*W2[j][k]
    __shared__ float      sq[4];     // q[k]    = .5*sum_j b1[j]*W2[j][k] + b2[k]
    __shared__ float      sWv[4];
    __shared__ float      swsum[8];
    __shared__ bool       is_last;

    const int tid = threadIdx.x;
    const long long gid = (long long)blockIdx.x * blockDim.x + tid;
    const long long r0  = gid << 2;   // 4 rows per thread
    const bool full = (r0 + 4 <= B);

    // issue data loads early (overlap with weight staging)
    float4 xA, xB, yA, yB, eA, eB;
    if (full) {
        xA = *reinterpret_cast<const float4*>(x  + (r0 << 1));
        xB = *reinterpret_cast<const float4*>(x  + (r0 << 1) + 4);
        yA = *reinterpret_cast<const float4*>(y  + (r0 << 1));
        yB = *reinterpret_cast<const float4*>(y  + (r0 << 1) + 4);
        eA = *reinterpret_cast<const float4*>(eps + (r0 << 1));
        eB = *reinterpret_cast<const float4*>(eps + (r0 << 1) + 4);
    }

    if (tid < 64) {
        float a = W1[tid];        // W1 row-major [2,64]
        float b = W1[64 + tid];
        sW1[tid].x = pack2(a, a);
        sW1[tid].y = pack2(b, b);
        float bb = b1[tid];
        sB1[tid] = pack2(bb, bb);
        float4 w2 = reinterpret_cast<const float4*>(W2)[tid];   // W2 [64,4]
        float h0 = 0.5f * w2.x, h1 = 0.5f * w2.y, h2 = 0.5f * w2.z, h3 = 0.5f * w2.w;
        sW2a[tid].x = pack2(h0, h0);
        sW2a[tid].y = pack2(h1, h1);
        sW2b[tid].x = pack2(h2, h2);
        sW2b[tid].y = pack2(h3, h3);
    }
    if (tid >= 64 && tid < 72) {          // P entries
        int i = (tid - 64) >> 2, k = (tid - 64) & 3;
        float acc = 0.0f;
        #pragma unroll 8
        for (int j = 0; j < 64; j++) acc = fmaf(W1[i * 64 + j], W2[4 * j + k], acc);
        sP[(tid - 64)] = 0.5f * acc;
    }
    if (tid >= 72 && tid < 76) {          // q entries
        int k = tid - 72;
        float acc = 0.0f;
        #pragma unroll 8
        for (int j = 0; j < 64; j++) acc = fmaf(b1[j], W2[4 * j + k], acc);
        sq[k] = fmaf(0.5f, acc, b2[k]);
    }
    if (tid >= 76 && tid < 80) sWv[tid - 76] = Wv[tid - 76];
    __syncthreads();

    float lacc = 0.0f;

    if (full) {
        ull x0A = pack2(xA.x, xA.z), x1A = pack2(xA.y, xA.w);
        ull x0B = pack2(xB.x, xB.z), x1B = pack2(xB.y, xB.w);

        // init accumulators with the per-row linear part:  P^T x + q
        ull p00 = pack2(sP[0], sP[0]), p01 = pack2(sP[1], sP[1]);
        ull p02 = pack2(sP[2], sP[2]), p03 = pack2(sP[3], sP[3]);
        ull p10 = pack2(sP[4], sP[4]), p11 = pack2(sP[5], sP[5]);
        ull p12 = pack2(sP[6], sP[6]), p13 = pack2(sP[7], sP[7]);
        ull q0 = pack2(sq[0], sq[0]), q1 = pack2(sq[1], sq[1]);
        ull q2 = pack2(sq[2], sq[2]), q3 = pack2(sq[3], sq[3]);

        ull a0A = fma2(x0A, p00, fma2(x1A, p10, q0));
        ull a1A = fma2(x0A, p01, fma2(x1A, p11, q1));
        ull a2A = fma2(x0A, p02, fma2(x1A, p12, q2));
        ull a3A = fma2(x0A, p03, fma2(x1A, p13, q3));
        ull a0B = fma2(x0B, p00, fma2(x1B, p10, q0));
        ull a1B = fma2(x0B, p01, fma2(x1B, p11, q1));
        ull a2B = fma2(x0B, p02, fma2(x1B, p12, q2));
        ull a3B = fma2(x0B, p03, fma2(x1B, p13, q3));

        #pragma unroll
        for (int j = 0; j < 64; j++) {
            ulonglong2 w1 = sW1[j];     // LDS.128 broadcast
            ull bb = sB1[j];            // LDS.64 broadcast
            ull uA = fma2(x0A, w1.x, fma2(x1A, w1.y, bb));
            ull uB = fma2(x0B, w1.x, fma2(x1B, w1.y, bb));
            ull hA = uA & ABS2_MASK;    // |u| on both halves: 2x LOP3, in place
            ull hB = uB & ABS2_MASK;
            ulonglong2 wa = sW2a[j];    // LDS.128
            ulonglong2 wb = sW2b[j];    // LDS.128
            a0A = fma2(hA, wa.x, a0A);
            a1A = fma2(hA, wa.y, a1A);
            a2A = fma2(hA, wb.x, a2A);
            a3A = fma2(hA, wb.y, a3A);
            a0B = fma2(hB, wa.x, a0B);
            a1B = fma2(hB, wa.y, a1B);
            a2B = fma2(hB, wb.x, a2B);
            a3B = fma2(hB, wb.y, a3B);
        }

        float mu0[4], mu1[4], lv0[4], lv1[4];
        unpack2(a0A, mu0[0], mu0[1]); unpack2(a0B, mu0[2], mu0[3]);
        unpack2(a1A, mu1[0], mu1[1]); unpack2(a1B, mu1[2], mu1[3]);
        unpack2(a2A, lv0[0], lv0[1]); unpack2(a2B, lv0[2], lv0[3]);
        unpack2(a3A, lv1[0], lv1[1]); unpack2(a3B, lv1[2], lv1[3]);

        const float xs0[4] = {xA.x, xA.z, xB.x, xB.z};
        const float xs1[4] = {xA.y, xA.w, xB.y, xB.w};
        const float ys0[4] = {yA.x, yA.z, yB.x, yB.z};
        const float ys1[4] = {yA.y, yA.w, yB.y, yB.w};
        const float es0[4] = {eA.x, eA.z, eB.x, eB.z};
        const float es1[4] = {eA.y, eA.w, eB.y, eB.w};

        float f0[4], f1[4];
        #pragma unroll
        for (int r = 0; r < 4; r++) {
            lacc += row_epilogue(xs0[r], xs1[r], mu0[r], mu1[r], lv0[r], lv1[r],
                                 ys0[r], ys1[r], es0[r], es1[r], sWv, f0[r], f1[r]);
        }

        *reinterpret_cast<float4*>(out + (r0 << 1))     = make_float4(f0[0], f1[0], f0[1], f1[1]);
        *reinterpret_cast<float4*>(out + (r0 << 1) + 4) = make_float4(f0[2], f1[2], f0[3], f1[3]);
    } else if (r0 < B) {
        // tail path (B not multiple of 4): scalar, relu form, global weights
        for (long long r = r0; r < B; ++r) {
            float x0 = x[2 * r], x1 = x[2 * r + 1];
            float acc0 = b2[0], acc1 = b2[1], acc2 = b2[2], acc3 = b2[3];
            for (int j = 0; j < 64; j++) {
                float h = fmaxf(fmaf(x0, W1[j], fmaf(x1, W1[64 + j], b1[j])), 0.0f);
                acc0 = fmaf(h, W2[4 * j + 0], acc0);
                acc1 = fmaf(h, W2[4 * j + 1], acc1);
                acc2 = fmaf(h, W2[4 * j + 2], acc2);
                acc3 = fmaf(h, W2[4 * j + 3], acc3);
            }
            float ff0, ff1;
            lacc += row_epilogue(x0, x1, acc0, acc1, acc2, acc3,
                                 y[2 * r], y[2 * r + 1], eps[2 * r], eps[2 * r + 1],
                                 sWv, ff0, ff1);
            out[2 * r]     = ff0;
            out[2 * r + 1] = ff1;
        }
    }

    // block reduction of logp terms
    #pragma unroll
    for (int off = 16; off > 0; off >>= 1)
        lacc += __shfl_xor_sync(0xFFFFFFFFu, lacc, off);
    const int warp = tid >> 5, lane = tid & 31;
    if (lane == 0) swsum[warp] = lacc;
    __syncthreads();
    if (tid == 0) {
        float s = 0.0f;
        #pragma unroll
        for (int w = 0; w < 8; w++) s += swsum[w];
        g_partials[blockIdx.x] = s;
        __threadfence();
        int n = atomicAdd(&g_count, 1);
        is_last = (n == (int)gridDim.x - 1);
    }
    __syncthreads();

    // last block: final deterministic reduction + self-reset of the counter
    if (is_last) {
        __threadfence();
        const int nb = (int)gridDim.x;
        double s = 0.0;
        for (int i = tid; i < nb; i += 256)
            s += (double)g_partials[i];
        __shared__ double sm[256];
        sm[tid] = s;
        __syncthreads();
        for (int off = 128; off > 0; off >>= 1) {
            if (tid < off) sm[tid] += sm[tid + off];
            __syncthreads();
        }
        if (tid == 0) {
            out[2 * B] = (float)(0.5 * sm[0] + (double)B * 1.8378770664093454836);
            g_count = 0;   // reset for next graph replay
        }
    }
}

extern "C" void kernel_launch(void* const* d_in, const int* in_sizes, int n_in,
                              void* d_out, int out_size)
{
    const float* x   = (const float*)d_in[0];
    const float* y   = (const float*)d_in[1];
    const float* eps = (const float*)d_in[2];
    const float* W1  = (const float*)d_in[3];
    const float* b1  = (const float*)d_in[4];
    const float* W2  = (const float*)d_in[5];
    const float* b2  = (const float*)d_in[6];
    const float* Wv  = (const float*)d_in[7];

    const long long B = (long long)in_sizes[0] / 2;
    const long long nthreads = (B + 3) >> 2;
    const int grid = (int)((nthreads + 255) >> 8);   // B=2^21 -> 2048 blocks

    mdn_kernel<<<grid, 256>>>(x, y, eps, W1, b1, W2, b2, Wv, (float*)d_out, B);
}

// round 8
// speedup vs baseline: 1.2184x; 1.2184x over previous
#include <cuda_runtime.h>
#include <cuda_bf16.h>

typedef unsigned long long ull;

#define BETA_F   0.99f
#define EPS_V_F  1e-3f
#define ABS2_MASK 0x7FFFFFFF7FFFFFFFull

// per-block partial sums + completion counter (deterministic single-kernel reduction)
__device__ float g_partials[16384];
__device__ int   g_count = 0;

// ---------- packed f32x2 helpers ----------
__device__ __forceinline__ ull pack2(float lo, float hi) {
    ull r;
    asm("mov.b64 %0, {%1, %2};" : "=l"(r) : "f"(lo), "f"(hi));
    return r;
}
__device__ __forceinline__ void unpack2(ull v, float& lo, float& hi) {
    asm("mov.b64 {%0, %1}, %2;" : "=f"(lo), "=f"(hi) : "l"(v));
}
__device__ __forceinline__ ull fma2(ull a, ull b, ull c) {
    ull d;
    asm("fma.rn.f32x2 %0, %1, %2, %3;" : "=l"(d) : "l"(a), "l"(b), "l"(c));
    return d;
}

// ---------- per-row epilogue ----------
__device__ __forceinline__ float row_epilogue(
    float x0, float x1,
    float mu0, float mu1, float l0, float l1,
    float y0, float y1, float e0, float e1,
    const float* __restrict__ wv,
    float& f0, float& f1)
{
    float u0 = fmaf(x1, wv[2], x0 * wv[0]);
    float u1 = fmaf(x1, wv[3], x0 * wv[1]);
    float vx = fmaf(u1, u1, fmaf(u0, u0, EPS_V_F));
    float m0 = fmaf(mu1, wv[2], mu0 * wv[0]);
    float m1 = fmaf(mu1, wv[3], mu0 * wv[1]);
    float vmu = fmaf(m1, m1, fmaf(m0, m0, EPS_V_F));
    float bvx = BETA_F * vx;
    float s   = __fdividef(fminf(bvx, vmu), vmu);
    float ms0 = mu0 * s;
    float ms1 = mu1 * s;
    float sd0 = __expf(0.5f * l0);
    float sd1 = __expf(0.5f * l1);
    float iv0 = __expf(-l0);
    float iv1 = __expf(-l1);
    f0 = fmaf(sd0, e0, ms0);
    f1 = fmaf(sd1, e1, ms1);
    float d0 = y0 - ms0;
    float d1 = y1 - ms1;
    return fmaf(d0 * d0, iv0, fmaf(d1 * d1, iv1, l0 + l1));
}

// ---------- fused kernel: MLP (abs form, j-pair packed) + epilogue + reduction ----------
__global__ __launch_bounds__(256) void mdn_kernel(
    const float* __restrict__ x, const float* __restrict__ y, const float* __restrict__ eps,
    const float* __restrict__ W1, const float* __restrict__ b1,
    const float* __restrict__ W2, const float* __restrict__ b2,
    const float* __restrict__ Wv,
    float* __restrict__ out, long long B)
{
    // relu(u) = (u + |u|)/2 ; out = P^T x + q + sum_j (.5 w2_j)|u_j|
    // j-pair packing: f32x2 holds hidden units (2jj, 2jj+1); x is register-duplicated.
    __shared__ ulonglong2 sL1[32];   // .x = (W1[0][2jj],W1[0][2jj+1]), .y = (W1[1][...])
    __shared__ ull        sB1[32];   // (b1[2jj], b1[2jj+1])
    __shared__ ulonglong2 sW2e[32];  // .x = col0 pair (*.5), .y = col1 pair
    __shared__ ulonglong2 sW2f[32];  // .x = col2 pair, .y = col3 pair
    __shared__ float      sPq[12];   // P[i*4+k] (e<8, *.5), q[k] (e=8..11)
    __shared__ float      sWv[4];
    __shared__ float      swsum[8];
    __shared__ bool       is_last;

    const int tid = threadIdx.x;
    const long long gid = (long long)blockIdx.x * blockDim.x + tid;
    const long long r0  = gid << 2;   // 4 rows per thread
    const bool full = (r0 + 4 <= B);

    // x loads early (only 2 front-batched LDG.128); y/eps deferred to epilogue
    float4 xA, xB;
    if (full) {
        xA = *reinterpret_cast<const float4*>(x + (r0 << 1));
        xB = *reinterpret_cast<const float4*>(x + (r0 << 1) + 4);
    }

    if (tid < 32) {
        const int jj = tid;
        float2 w1r0 = *reinterpret_cast<const float2*>(W1 + 2 * jj);
        float2 w1r1 = *reinterpret_cast<const float2*>(W1 + 64 + 2 * jj);
        float2 bp   = *reinterpret_cast<const float2*>(b1 + 2 * jj);
        float4 w2a  = *reinterpret_cast<const float4*>(W2 + 8 * jj);       // row 2jj
        float4 w2b  = *reinterpret_cast<const float4*>(W2 + 8 * jj + 4);   // row 2jj+1
        sL1[jj].x = pack2(w1r0.x, w1r0.y);
        sL1[jj].y = pack2(w1r1.x, w1r1.y);
        sB1[jj]   = pack2(bp.x, bp.y);
        sW2e[jj].x = pack2(0.5f * w2a.x, 0.5f * w2b.x);
        sW2e[jj].y = pack2(0.5f * w2a.y, 0.5f * w2b.y);
        sW2f[jj].x = pack2(0.5f * w2a.z, 0.5f * w2b.z);
        sW2f[jj].y = pack2(0.5f * w2a.w, 0.5f * w2b.w);
    } else if (tid < 128) {
        // P/q entries: 12 entries x 8 threads, shfl-reduced (parallel prologue)
        const int idx = tid - 32;       // 0..95
        const int e = idx >> 3;         // 0..11
        const int g = idx & 7;
        float acc = 0.0f;
        if (e < 8) {
            const int i = e >> 2, k = e & 3;
            #pragma unroll
            for (int j = g; j < 64; j += 8)
                acc = fmaf(W1[i * 64 + j], W2[4 * j + k], acc);
        } else {
            const int k = e - 8;
            #pragma unroll
            for (int j = g; j < 64; j += 8)
                acc = fmaf(b1[j], W2[4 * j + k], acc);
        }
        acc += __shfl_xor_sync(0xFFFFFFFFu, acc, 4);
        acc += __shfl_xor_sync(0xFFFFFFFFu, acc, 2);
        acc += __shfl_xor_sync(0xFFFFFFFFu, acc, 1);
        if (g == 0) {
            if (e < 8) sPq[e] = 0.5f * acc;
            else       sPq[e] = fmaf(0.5f, acc, b2[e - 8]);
        }
    } else if (tid < 132) {
        sWv[tid - 128] = Wv[tid - 128];
    }
    __syncthreads();

    float lacc = 0.0f;

    if (full) {
        // register-duplicated x for the 4 rows
        ull xd0[4], xd1[4];
        xd0[0] = pack2(xA.x, xA.x); xd1[0] = pack2(xA.y, xA.y);
        xd0[1] = pack2(xA.z, xA.z); xd1[1] = pack2(xA.w, xA.w);
        xd0[2] = pack2(xB.x, xB.x); xd1[2] = pack2(xB.y, xB.y);
        xd0[3] = pack2(xB.z, xB.z); xd1[3] = pack2(xB.w, xB.w);

        ull acc0[4] = {0, 0, 0, 0};
        ull acc1[4] = {0, 0, 0, 0};
        ull acc2[4] = {0, 0, 0, 0};
        ull acc3[4] = {0, 0, 0, 0};

        #pragma unroll 8
        for (int jj = 0; jj < 32; jj++) {
            const ulonglong2 w1 = sL1[jj];   // LDS.128 broadcast
            const ull        bb = sB1[jj];   // LDS.64
            const ulonglong2 we = sW2e[jj];  // LDS.128
            const ulonglong2 wf = sW2f[jj];  // LDS.128
            #pragma unroll
            for (int r = 0; r < 4; r++) {
                ull u = fma2(xd0[r], w1.x, fma2(xd1[r], w1.y, bb));
                ull h = u & ABS2_MASK;       // |u| on both halves
                acc0[r] = fma2(h, we.x, acc0[r]);
                acc1[r] = fma2(h, we.y, acc1[r]);
                acc2[r] = fma2(h, wf.x, acc2[r]);
                acc3[r] = fma2(h, wf.y, acc3[r]);
            }
        }

        // fold halves (even-j + odd-j partials) + linear part P^T x + q
        const float p00 = sPq[0], p01 = sPq[1], p02 = sPq[2], p03 = sPq[3];
        const float p10 = sPq[4], p11 = sPq[5], p12 = sPq[6], p13 = sPq[7];
        const float q0 = sPq[8], q1 = sPq[9], q2 = sPq[10], q3 = sPq[11];
        const float xs0[4] = {xA.x, xA.z, xB.x, xB.z};
        const float xs1[4] = {xA.y, xA.w, xB.y, xB.w};

        float mu0[4], mu1[4], lv0[4], lv1[4];
        #pragma unroll
        for (int r = 0; r < 4; r++) {
            float lo, hi;
            unpack2(acc0[r], lo, hi); mu0[r] = fmaf(xs0[r], p00, fmaf(xs1[r], p10, q0)) + (lo + hi);
            unpack2(acc1[r], lo, hi); mu1[r] = fmaf(xs0[r], p01, fmaf(xs1[r], p11, q1)) + (lo + hi);
            unpack2(acc2[r], lo, hi); lv0[r] = fmaf(xs0[r], p02, fmaf(xs1[r], p12, q2)) + (lo + hi);
            unpack2(acc3[r], lo, hi); lv1[r] = fmaf(xs0[r], p03, fmaf(xs1[r], p13, q3)) + (lo + hi);
        }

        // late data loads
        const float4 yA = *reinterpret_cast<const float4*>(y  + (r0 << 1));
        const float4 yB = *reinterpret_cast<const float4*>(y  + (r0 << 1) + 4);
        const float4 eA = *reinterpret_cast<const float4*>(eps + (r0 << 1));
        const float4 eB = *reinterpret_cast<const float4*>(eps + (r0 << 1) + 4);
        const float ys0[4] = {yA.x, yA.z, yB.x, yB.z};
        const float ys1[4] = {yA.y, yA.w, yB.y, yB.w};
        const float es0[4] = {eA.x, eA.z, eB.x, eB.z};
        const float es1[4] = {eA.y, eA.w, eB.y, eB.w};

        float f0[4], f1[4];
        #pragma unroll
        for (int r = 0; r < 4; r++) {
            lacc += row_epilogue(xs0[r], xs1[r], mu0[r], mu1[r], lv0[r], lv1[r],
                                 ys0[r], ys1[r], es0[r], es1[r], sWv, f0[r], f1[r]);
        }

        *reinterpret_cast<float4*>(out + (r0 << 1))     = make_float4(f0[0], f1[0], f0[1], f1[1]);
        *reinterpret_cast<float4*>(out + (r0 << 1) + 4) = make_float4(f0[2], f1[2], f0[3], f1[3]);
    } else if (r0 < B) {
        // tail path (B not multiple of 4): scalar, relu form, global weights
        for (long long r = r0; r < B; ++r) {
            float x0 = x[2 * r], x1 = x[2 * r + 1];
            float a0 = b2[0], a1 = b2[1], a2 = b2[2], a3 = b2[3];
            for (int j = 0; j < 64; j++) {
                float h = fmaxf(fmaf(x0, W1[j], fmaf(x1, W1[64 + j], b1[j])), 0.0f);
                a0 = fmaf(h, W2[4 * j + 0], a0);
                a1 = fmaf(h, W2[4 * j + 1], a1);
                a2 = fmaf(h, W2[4 * j + 2], a2);
                a3 = fmaf(h, W2[4 * j + 3], a3);
            }
            float ff0, ff1;
            lacc += row_epilogue(x0, x1, a0, a1, a2, a3,
                                 y[2 * r], y[2 * r + 1], eps[2 * r], eps[2 * r + 1],
                                 sWv, ff0, ff1);
            out[2 * r]     = ff0;
            out[2 * r + 1] = ff1;
        }
    }

    // block reduction of logp terms
    #pragma unroll
    for (int off = 16; off > 0; off >>= 1)
        lacc += __shfl_xor_sync(0xFFFFFFFFu, lacc, off);
    const int warp = tid >> 5, lane = tid & 31;
    if (lane == 0) swsum[warp] = lacc;
    __syncthreads();
    if (tid == 0) {
        float s = 0.0f;
        #pragma unroll
        for (int w = 0; w < 8; w++) s += swsum[w];
        g_partials[blockIdx.x] = s;
        __threadfence();
        int n = atomicAdd(&g_count, 1);
        is_last = (n == (int)gridDim.x - 1);
    }
    __syncthreads();

    // last block: deterministic final reduction + counter self-reset (graph replay safe)
    if (is_last) {
        __threadfence();
        const int nb = (int)gridDim.x;
        double s = 0.0;
        for (int i = tid; i < nb; i += 256)
            s += (double)g_partials[i];
        __shared__ double sm[256];
        sm[tid] = s;
        __syncthreads();
        for (int off = 128; off > 0; off >>= 1) {
            if (tid < off) sm[tid] += sm[tid + off];
            __syncthreads();
        }
        if (tid == 0) {
            out[2 * B] = (float)(0.5 * sm[0] + (double)B * 1.8378770664093454836);
            g_count = 0;
        }
    }
}

extern "C" void kernel_launch(void* const* d_in, const int* in_sizes, int n_in,
                              void* d_out, int out_size)
{
    const float* x   = (const float*)d_in[0];
    const float* y   = (const float*)d_in[1];
    const float* eps = (const float*)d_in[2];
    const float* W1  = (const float*)d_in[3];
    const float* b1  = (const float*)d_in[4];
    const float* W2  = (const float*)d_in[5];
    const float* b2  = (const float*)d_in[6];
    const float* Wv  = (const float*)d_in[7];

    const long long B = (long long)in_sizes[0] / 2;
    const long long nthreads = (B + 3) >> 2;
    const int grid = (int)((nthreads + 255) >> 8);   // B=2^21 -> 2048 blocks

    mdn_kernel<<<grid, 256>>>(x, y, eps, W1, b1, W2, b2, Wv, (float*)d_out, B);
}